// round 15
// baseline (speedup 1.0000x reference)
#include <cuda_runtime.h>
#include <cuda_fp16.h>
#include <cstdint>

#define NBATCH 4096
#define NTOK   64
#define NDIM   256
#define NHEADS 8
#define HD     32
#define NROWS  (NBATCH * NTOK)   // 262144

// ---------------- device scratch ---------------------------------------------
__device__ __align__(16) __half g_xf[(size_t)NROWS * 256];
__device__ __align__(16) __half g_of[(size_t)NROWS * 256];
__device__ __align__(16) __half g_wqf[768 * 256];
__device__ __align__(16) __half g_wpf[256 * 256];
__device__ __align__(16) __half g_qf[(size_t)NBATCH * NHEADS * NTOK * HD];
__device__ __align__(16) __half g_kf[(size_t)NBATCH * NHEADS * NTOK * HD];
__device__ __align__(16) __half g_vf[(size_t)NBATCH * NHEADS * NTOK * HD];
__device__ float g_bias[NHEADS * NTOK * NTOK];

// ---------------- helpers ----------------------------------------------------
__device__ __forceinline__ uint32_t s2u(const void* p) {
    return (uint32_t)__cvta_generic_to_shared(p);
}
#define LDM4(r0, r1, r2, r3, addr)                                              \
    asm volatile("ldmatrix.sync.aligned.m8n8.x4.shared.b16 {%0,%1,%2,%3}, [%4];"\
                 : "=r"(r0), "=r"(r1), "=r"(r2), "=r"(r3) : "r"(addr))
#define LDM4T(r0, r1, r2, r3, addr)                                             \
    asm volatile("ldmatrix.sync.aligned.m8n8.x4.trans.shared.b16 {%0,%1,%2,%3}, [%4];"\
                 : "=r"(r0), "=r"(r1), "=r"(r2), "=r"(r3) : "r"(addr))
#define CP16(dst, src)                                                          \
    asm volatile("cp.async.cg.shared.global [%0], [%1], 16;" :: "r"(dst), "l"(src))
#define CP_COMMIT() asm volatile("cp.async.commit_group;")
#define CP_WAIT0()  asm volatile("cp.async.wait_group 0;")

__device__ __forceinline__ void mma16h(float* c, const uint32_t* a, const uint32_t* b) {
    asm volatile(
        "mma.sync.aligned.m16n8k16.row.col.f32.f16.f16.f32 "
        "{%0,%1,%2,%3}, {%4,%5,%6,%7}, {%8,%9}, {%0,%1,%2,%3};"
        : "+f"(c[0]), "+f"(c[1]), "+f"(c[2]), "+f"(c[3])
        : "r"(a[0]), "r"(a[1]), "r"(a[2]), "r"(a[3]), "r"(b[0]), "r"(b[1]));
}

// ---------------------------------------------------------------------------
// One merged prep kernel.
// Block ranges: [0,65536) x | [65536,66304) wq | [66304,66560) wp | [66560,66688) bias
// ---------------------------------------------------------------------------
__global__ void prep_all(const float* __restrict__ x,
                         const float* __restrict__ wq, const float* __restrict__ wkv,
                         const float* __restrict__ pw,
                         const float* __restrict__ bias_table,
                         const int* __restrict__ rel_idx)
{
    const int bid = blockIdx.x;
    if (bid < 65536) {
        size_t i = (size_t)bid * 256 + threadIdx.x;
        float4 v = ((const float4*)x)[i];
        __half2 a = __floats2half2_rn(v.x, v.y);
        __half2 b = __floats2half2_rn(v.z, v.w);
        ((uint2*)g_xf)[i] = make_uint2(*(uint32_t*)&a, *(uint32_t*)&b);
    } else if (bid < 66304) {
        int idx = (bid - 65536) * 256 + threadIdx.x;   // [0, 196608)
        int c = idx >> 8, k = idx & 255;
        float v = (c < 256) ? wq[k * 256 + c] : wkv[k * 512 + (c - 256)];
        g_wqf[idx] = __float2half_rn(v);
    } else if (bid < 66560) {
        int idx = (bid - 66304) * 256 + threadIdx.x;   // [0, 65536)
        int c = idx >> 8, k = idx & 255;
        g_wpf[idx] = __float2half_rn(pw[k * 256 + c]);
    } else {
        int idx = (bid - 66560) * 256 + threadIdx.x;   // [0, 32768)
        int h = idx >> 12, rm = idx & 4095;
        g_bias[idx] = bias_table[rel_idx[rm] * NHEADS + h];
    }
}

// ---------------------------------------------------------------------------
// fp16 GEMM (R14, unchanged): C[128x128] = A[128x256] @ W^T. 40KB, 2 CTA/SM.
// 256 thr / 8 warps (2m x 4n), warp tile 64x32, BK=32, 2-stage,
// single-barrier schedule: wait0 -> sync -> load(s+1) -> compute(s).
// mode 0: qkv -> q/k/v single fp16 (q scaled). mode 1: proj -> fp32 out.
// ---------------------------------------------------------------------------
__global__ __launch_bounds__(256) void mm_fp16(
    const __half* __restrict__ A, const __half* __restrict__ W,
    const float* __restrict__ bq, const float* __restrict__ bkv,
    const float* __restrict__ pb, float* __restrict__ outp, int mode)
{
    extern __shared__ __align__(16) char sm[];
    const uint32_t sb = s2u(sm);
    const int t = threadIdx.x;
    const int lane = t & 31, wid = t >> 5;
    const int wm = wid & 1, wn = wid >> 1;
    const int gid = lane >> 2, t4 = lane & 3;
    const size_t row0 = (size_t)blockIdx.y * 128;
    const int col0 = blockIdx.x * 128;

    float c[4][4][4];
#pragma unroll
    for (int mt = 0; mt < 4; mt++)
#pragma unroll
        for (int nt = 0; nt < 4; nt++)
#pragma unroll
            for (int i = 0; i < 4; i++) c[mt][nt][i] = 0.f;

#define LOADG(S, BUF)                                                            \
    do {                                                                         \
        const int k0 = (S) * 32;                                                 \
        _Pragma("unroll")                                                        \
        for (int j = 0; j < 2; j++) {                                            \
            const int idx = j * 256 + t;                                         \
            const int r = idx >> 2, q = idx & 3;                                 \
            const uint32_t doff = (uint32_t)((BUF) * 10240 + r * 80 + q * 16);   \
            CP16(sb + doff,         A + (row0 + r) * 256 + k0 + q * 8);          \
            CP16(sb + 20480 + doff, W + (size_t)(col0 + r) * 256 + k0 + q * 8);  \
        }                                                                        \
        CP_COMMIT();                                                             \
    } while (0)

    LOADG(0, 0);

    const int arow = (lane & 7) + ((lane >> 3) & 1) * 8;
    const int aksh = ((lane >> 4) & 1) * 8;
    const int brow = (lane & 7) + ((lane >> 4) & 1) * 8;
    const int bksh = ((lane >> 3) & 1) * 8;

    for (int s = 0; s < 8; s++) {
        const int cur = s & 1;
        CP_WAIT0();
        __syncthreads();
        if (s < 7) LOADG(s + 1, cur ^ 1);
#pragma unroll
        for (int kk = 0; kk < 2; kk++) {
            const int kb = kk * 16;
            uint32_t a[4][4];
#pragma unroll
            for (int mt = 0; mt < 4; mt++) {
                const int r = wm * 64 + mt * 16 + arow;
                const uint32_t aoff = (uint32_t)(cur * 10240 + r * 80 + (kb + aksh) * 2);
                LDM4(a[mt][0], a[mt][1], a[mt][2], a[mt][3], sb + aoff);
            }
#pragma unroll
            for (int ntp = 0; ntp < 2; ntp++) {
                const int nr = wn * 32 + ntp * 16 + brow;
                const uint32_t boff =
                    (uint32_t)(20480 + cur * 10240 + nr * 80 + (kb + bksh) * 2);
                uint32_t b[4];
                LDM4(b[0], b[1], b[2], b[3], sb + boff);
#pragma unroll
                for (int mt = 0; mt < 4; mt++) {
                    mma16h(c[mt][2 * ntp],     a[mt], b);
                    mma16h(c[mt][2 * ntp + 1], a[mt], b + 2);
                }
            }
        }
    }

    // ---- epilogue ----
#pragma unroll
    for (int mt = 0; mt < 4; mt++) {
        const int rbase = wm * 64 + mt * 16 + gid;
#pragma unroll
        for (int h8 = 0; h8 < 2; h8++) {
            const size_t grow = row0 + rbase + h8 * 8;
#pragma unroll
            for (int nt = 0; nt < 4; nt++) {
                const int cib = wn * 32 + nt * 8 + t4 * 2;
                const float v0 = c[mt][nt][h8 * 2 + 0];
                const float v1 = c[mt][nt][h8 * 2 + 1];
                if (mode) {
                    const float2 pbv = *(const float2*)(pb + col0 + cib);
                    float2 o2; o2.x = v0 + pbv.x; o2.y = v1 + pbv.y;
                    *(float2*)(outp + grow * 256 + col0 + cib) = o2;
                } else {
                    const int region = col0 >> 8;          // 0=q 1=k 2=v
                    const int c2 = col0 - (region << 8) + cib;
                    const float* bias = (region == 0) ? bq
                                       : (region == 1) ? bkv : (bkv + 256);
                    const float2 bv = *(const float2*)(bias + c2);
                    const float scl = (region == 0) ? 0.17677669529663687f : 1.0f;
                    __half* dst = (region == 0) ? g_qf : (region == 1) ? g_kf : g_vf;
                    const int win = (int)(grow >> 6), nn = (int)(grow & 63);
                    const int hh = c2 >> 5, d = c2 & 31;
                    const size_t di = (((size_t)win * NHEADS + hh) * NTOK + nn) * HD + d;
                    __half2 p = __floats2half2_rn((v0 + bv.x) * scl,
                                                  (v1 + bv.y) * scl);
                    *(uint32_t*)(dst + di) = *(uint32_t*)&p;
                }
            }
        }
    }
#undef LOADG
}

// ---------------------------------------------------------------------------
// Attention, batched: one block = one window (8 heads processed sequentially,
// double-buffered Q/K/V via cp.async). 128 thr / 4 warps. Per-unit math is
// byte-identical to R14's attn_f16.
// smem bytes: QKV buf0 @0, buf1 @15360 (each: Q+0, K+5120, V+10240);
//             S 30720 + wid*2304.  total 39936.
// ---------------------------------------------------------------------------
__global__ __launch_bounds__(128) void attn_f16(const float* __restrict__ w)
{
    extern __shared__ __align__(16) char sm[];
    const uint32_t sb = s2u(sm);
    const int win = blockIdx.x;
    const int t = threadIdx.x, lane = t & 31, wid = t >> 5;
    const int gid = lane >> 2, t4 = lane & 3;

#define LOADU(U, BUF)                                                            \
    do {                                                                         \
        const size_t gbase = ((size_t)win * NHEADS + (U)) * 2048;                \
        const uint32_t bbase = (uint32_t)(BUF) * 15360;                          \
        _Pragma("unroll")                                                        \
        for (int j = 0; j < 2; j++) {                                            \
            const int idx = j * 128 + t;                                         \
            const int r = idx >> 2, q = idx & 3;                                 \
            const uint32_t doff = bbase + (uint32_t)(r * 80 + q * 16);           \
            const size_t soff = gbase + r * 32 + q * 8;                          \
            CP16(sb + doff,         g_qf + soff);                                \
            CP16(sb + 5120 + doff,  g_kf + soff);                                \
            CP16(sb + 10240 + doff, g_vf + soff);                                \
        }                                                                        \
        CP_COMMIT();                                                             \
    } while (0)

    LOADU(0, 0);

    // mixing weights (loop-invariant)
    const float w0 = w[0], w1 = w[1];
    const float wmx = fmaxf(w0, w1);
    const float e0 = __expf(w0 - wmx), e1 = __expf(w1 - wmx);
    const float winv = 1.f / (e0 + e1);
    const float ww0 = e0 * winv, ww1 = e1 * winv;

    const int arow = (lane & 7) + ((lane >> 3) & 1) * 8;
    const int aksh = ((lane >> 4) & 1) * 8;
    const int brow = (lane & 7) + ((lane >> 4) & 1) * 8;
    const int bksh = ((lane >> 3) & 1) * 8;
    const int vrow = (lane & 7) + ((lane >> 3) & 1) * 8;
    const int vcsh = ((lane >> 4) & 1) * 8;
    const int r0 = wid * 16 + gid;
    const uint32_t sh0 = 30720 + wid * 2304;

    for (int u = 0; u < NHEADS; u++) {
        const int cur = u & 1;
        const uint32_t qb = (uint32_t)cur * 15360;
        CP_WAIT0();          // unit u landed
        __syncthreads();     // all warps done with unit u-1 (buffer cur^1 dead)
        if (u < NHEADS - 1) LOADU(u + 1, cur ^ 1);

        // ---- S = Q@K^T (single-term) ----
        float c[8][4];
#pragma unroll
        for (int nt = 0; nt < 8; nt++)
#pragma unroll
            for (int i = 0; i < 4; i++) c[nt][i] = 0.f;

#pragma unroll
        for (int kk = 0; kk < 2; kk++) {
            const int kb16 = kk * 16;
            uint32_t a[4];
            const uint32_t qoff =
                qb + (uint32_t)((wid * 16 + arow) * 80 + (kb16 + aksh) * 2);
            LDM4(a[0], a[1], a[2], a[3], sb + qoff);
#pragma unroll
            for (int ntp = 0; ntp < 4; ntp++) {
                const uint32_t koff =
                    qb + (uint32_t)(5120 + (ntp * 16 + brow) * 80 + (kb16 + bksh) * 2);
                uint32_t bk[4];
                LDM4(bk[0], bk[1], bk[2], bk[3], sb + koff);
                mma16h(c[2 * ntp],     a, bk);
                mma16h(c[2 * ntp + 1], a, bk + 2);
            }
        }

        // ---- bias add ----
        const float* b0p = g_bias + ((size_t)u * 64 + r0) * 64;
        const float* b1p = b0p + 8 * 64;
#pragma unroll
        for (int nt = 0; nt < 8; nt++) {
            const int cc = nt * 8 + 2 * t4;
            const float2 x0 = *(const float2*)(b0p + cc);
            const float2 x1 = *(const float2*)(b1p + cc);
            c[nt][0] += x0.x; c[nt][1] += x0.y;
            c[nt][2] += x1.x; c[nt][3] += x1.y;
        }

        // ---- softmax sums ----
        float p0 = 0.f, p1 = 0.f;
#pragma unroll
        for (int nt = 0; nt < 8; nt++) {
            p0 += __expf(c[nt][0]) + __expf(c[nt][1]);
            p1 += __expf(c[nt][2]) + __expf(c[nt][3]);
        }
        p0 += __shfl_xor_sync(0xFFFFFFFF, p0, 1);
        p0 += __shfl_xor_sync(0xFFFFFFFF, p0, 2);
        p1 += __shfl_xor_sync(0xFFFFFFFF, p1, 1);
        p1 += __shfl_xor_sync(0xFFFFFFFF, p1, 2);
        const float k00 = ww0 / p0, k01 = ww0 / p1;

        // ---- combined weights -> S single fp16 smem ----
#pragma unroll
        for (int nt = 0; nt < 8; nt++) {
            const int cc = nt * 8 + 2 * t4;
            const float q00 = fmaxf(c[nt][0], 0.f), q01 = fmaxf(c[nt][1], 0.f);
            const float q10 = fmaxf(c[nt][2], 0.f), q11 = fmaxf(c[nt][3], 0.f);
            const float a0 = __expf(c[nt][0]) * k00 + q00 * q00 * ww1;
            const float a1 = __expf(c[nt][1]) * k00 + q01 * q01 * ww1;
            const float a2 = __expf(c[nt][2]) * k01 + q10 * q10 * ww1;
            const float a3 = __expf(c[nt][3]) * k01 + q11 * q11 * ww1;
            __half2 h01 = __floats2half2_rn(a0, a1);
            __half2 h23 = __floats2half2_rn(a2, a3);
            *(uint32_t*)(sm + sh0 + gid * 144 + cc * 2) = *(uint32_t*)&h01;
            *(uint32_t*)(sm + sh0 + (gid + 8) * 144 + cc * 2) = *(uint32_t*)&h23;
        }
        __syncwarp();

        // ---- O = A @ V (single-term), V via ldmatrix.trans ----
        float o[4][4];
#pragma unroll
        for (int nt = 0; nt < 4; nt++)
#pragma unroll
            for (int i = 0; i < 4; i++) o[nt][i] = 0.f;

#pragma unroll
        for (int kc = 0; kc < 4; kc++) {
            const int kb16 = kc * 16;
            uint32_t a[4];
            const uint32_t soff = (uint32_t)(arow * 144 + (kb16 + aksh) * 2);
            LDM4(a[0], a[1], a[2], a[3], sb + sh0 + soff);
#pragma unroll
            for (int ntp = 0; ntp < 2; ntp++) {
                const uint32_t voff =
                    qb + (uint32_t)(10240 + (kb16 + vrow) * 80
                                    + (ntp * 16 + vcsh) * 2);
                uint32_t bv[4];
                LDM4T(bv[0], bv[1], bv[2], bv[3], sb + voff);
                mma16h(o[2 * ntp],     a, bv);
                mma16h(o[2 * ntp + 1], a, bv + 2);
            }
        }

        // ---- write O fp16 ----
        const size_t obase = ((size_t)win * 64) * 256 + u * 32;
#pragma unroll
        for (int nt = 0; nt < 4; nt++) {
            const int d = nt * 8 + 2 * t4;
            __half2 v0 = __floats2half2_rn(o[nt][0], o[nt][1]);
            __half2 v1 = __floats2half2_rn(o[nt][2], o[nt][3]);
            *(uint32_t*)(g_of + obase + (size_t)r0 * 256 + d) = *(uint32_t*)&v0;
            *(uint32_t*)(g_of + obase + (size_t)(r0 + 8) * 256 + d) = *(uint32_t*)&v1;
        }
    }
#undef LOADU
}

// ---------------------------------------------------------------------------
extern "C" void kernel_launch(void* const* d_in, const int* in_sizes, int n_in,
                              void* d_out, int out_size)
{
    const float* x   = (const float*)d_in[0];
    const float* wq  = (const float*)d_in[1];
    const float* bq  = (const float*)d_in[2];
    const float* wkv = (const float*)d_in[3];
    const float* bkv = (const float*)d_in[4];
    const float* bt  = (const float*)d_in[5];
    const float* w   = (const float*)d_in[6];
    const float* pw  = (const float*)d_in[7];
    const float* pb  = (const float*)d_in[8];
    const int*   ri  = (const int*)d_in[9];
    float* out = (float*)d_out;

    __half *xf, *of, *wqf, *wpf;
    cudaGetSymbolAddress((void**)&xf,  g_xf);
    cudaGetSymbolAddress((void**)&of,  g_of);
    cudaGetSymbolAddress((void**)&wqf, g_wqf);
    cudaGetSymbolAddress((void**)&wpf, g_wpf);

    prep_all<<<66688, 256>>>(x, wq, wkv, pw, bt, ri);
    mm_fp16<<<dim3(6, NROWS / 128), 256, 40960>>>(xf, wqf, bq, bkv,
                                                  nullptr, nullptr, 0);
    attn_f16<<<NBATCH, 128, 39936>>>(w);
    mm_fp16<<<dim3(2, NROWS / 128), 256, 40960>>>(of, wpf, nullptr, nullptr,
                                                  pb, out, 1);
}

// round 16
// speedup vs baseline: 1.0103x; 1.0103x over previous
#include <cuda_runtime.h>
#include <cuda_fp16.h>
#include <cstdint>

#define NBATCH 4096
#define NTOK   64
#define NDIM   256
#define NHEADS 8
#define HD     32
#define NROWS  (NBATCH * NTOK)   // 262144

// ---------------- device scratch ---------------------------------------------
__device__ __align__(16) __half g_xf[(size_t)NROWS * 256];
__device__ __align__(16) __half g_of[(size_t)NROWS * 256];
__device__ __align__(16) __half g_wqf[768 * 256];
__device__ __align__(16) __half g_wpf[256 * 256];
__device__ __align__(16) __half g_qf[(size_t)NBATCH * NHEADS * NTOK * HD];
__device__ __align__(16) __half g_kf[(size_t)NBATCH * NHEADS * NTOK * HD];
__device__ __align__(16) __half g_vf[(size_t)NBATCH * NHEADS * NTOK * HD];
__device__ float g_bias[NHEADS * NTOK * NTOK];

// ---------------- helpers ----------------------------------------------------
__device__ __forceinline__ uint32_t s2u(const void* p) {
    return (uint32_t)__cvta_generic_to_shared(p);
}
#define LDM4(r0, r1, r2, r3, addr)                                              \
    asm volatile("ldmatrix.sync.aligned.m8n8.x4.shared.b16 {%0,%1,%2,%3}, [%4];"\
                 : "=r"(r0), "=r"(r1), "=r"(r2), "=r"(r3) : "r"(addr))
#define LDM4T(r0, r1, r2, r3, addr)                                             \
    asm volatile("ldmatrix.sync.aligned.m8n8.x4.trans.shared.b16 {%0,%1,%2,%3}, [%4];"\
                 : "=r"(r0), "=r"(r1), "=r"(r2), "=r"(r3) : "r"(addr))
#define CP16(dst, src)                                                          \
    asm volatile("cp.async.cg.shared.global [%0], [%1], 16;" :: "r"(dst), "l"(src))
#define CP_COMMIT() asm volatile("cp.async.commit_group;")
#define CP_WAIT0()  asm volatile("cp.async.wait_group 0;")

__device__ __forceinline__ void mma16h(float* c, const uint32_t* a, const uint32_t* b) {
    asm volatile(
        "mma.sync.aligned.m16n8k16.row.col.f32.f16.f16.f32 "
        "{%0,%1,%2,%3}, {%4,%5,%6,%7}, {%8,%9}, {%0,%1,%2,%3};"
        : "+f"(c[0]), "+f"(c[1]), "+f"(c[2]), "+f"(c[3])
        : "r"(a[0]), "r"(a[1]), "r"(a[2]), "r"(a[3]), "r"(b[0]), "r"(b[1]));
}

// ---------------------------------------------------------------------------
// One merged prep kernel.
// Block ranges: [0,65536) x | [65536,66304) wq | [66304,66560) wp | [66560,66688) bias
// ---------------------------------------------------------------------------
__global__ void prep_all(const float* __restrict__ x,
                         const float* __restrict__ wq, const float* __restrict__ wkv,
                         const float* __restrict__ pw,
                         const float* __restrict__ bias_table,
                         const int* __restrict__ rel_idx)
{
    const int bid = blockIdx.x;
    if (bid < 65536) {
        size_t i = (size_t)bid * 256 + threadIdx.x;
        float4 v = ((const float4*)x)[i];
        __half2 a = __floats2half2_rn(v.x, v.y);
        __half2 b = __floats2half2_rn(v.z, v.w);
        ((uint2*)g_xf)[i] = make_uint2(*(uint32_t*)&a, *(uint32_t*)&b);
    } else if (bid < 66304) {
        int idx = (bid - 65536) * 256 + threadIdx.x;   // [0, 196608)
        int c = idx >> 8, k = idx & 255;
        float v = (c < 256) ? wq[k * 256 + c] : wkv[k * 512 + (c - 256)];
        g_wqf[idx] = __float2half_rn(v);
    } else if (bid < 66560) {
        int idx = (bid - 66304) * 256 + threadIdx.x;   // [0, 65536)
        int c = idx >> 8, k = idx & 255;
        g_wpf[idx] = __float2half_rn(pw[k * 256 + c]);
    } else {
        int idx = (bid - 66560) * 256 + threadIdx.x;   // [0, 32768)
        int h = idx >> 12, rm = idx & 4095;
        g_bias[idx] = bias_table[rel_idx[rm] * NHEADS + h];
    }
}

// ---------------------------------------------------------------------------
// fp16 GEMM, 128-thread CTAs: C[128x64] = A[128x256] @ W^T block.
// 4 warps (2m x 2n), warp tile 64x32 (inner loop identical to R14), BK=32,
// 2-stage, single-barrier schedule. smem: A buf*10240 | B 20480 + buf*5120;
// total 30720 B -> 4 CTAs/SM (RF-limited), 4 independent barrier domains.
// mode 0: qkv -> q/k/v single fp16 (q scaled). mode 1: proj -> fp32 out.
// ---------------------------------------------------------------------------
__global__ __launch_bounds__(128, 4) void mm_fp16(
    const __half* __restrict__ A, const __half* __restrict__ W,
    const float* __restrict__ bq, const float* __restrict__ bkv,
    const float* __restrict__ pb, float* __restrict__ outp, int mode)
{
    extern __shared__ __align__(16) char sm[];
    const uint32_t sb = s2u(sm);
    const int t = threadIdx.x;
    const int lane = t & 31, wid = t >> 5;
    const int wm = wid & 1, wn = wid >> 1;        // 2m x 2n
    const int gid = lane >> 2, t4 = lane & 3;
    const size_t row0 = (size_t)blockIdx.y * 128;
    const int col0 = blockIdx.x * 64;

    float c[4][4][4];
#pragma unroll
    for (int mt = 0; mt < 4; mt++)
#pragma unroll
        for (int nt = 0; nt < 4; nt++)
#pragma unroll
            for (int i = 0; i < 4; i++) c[mt][nt][i] = 0.f;

#define LOADG(S, BUF)                                                            \
    do {                                                                         \
        const int k0 = (S) * 32;                                                 \
        _Pragma("unroll")                                                        \
        for (int j = 0; j < 4; j++) {          /* A: 512 chunks / 128 thr */     \
            const int idx = j * 128 + t;                                         \
            const int r = idx >> 2, q = idx & 3;                                 \
            CP16(sb + (uint32_t)((BUF) * 10240 + r * 80 + q * 16),               \
                 A + (row0 + r) * 256 + k0 + q * 8);                             \
        }                                                                        \
        _Pragma("unroll")                                                        \
        for (int j = 0; j < 2; j++) {          /* B: 256 chunks / 128 thr */     \
            const int idx = j * 128 + t;                                         \
            const int r = idx >> 2, q = idx & 3;                                 \
            CP16(sb + (uint32_t)(20480 + (BUF) * 5120 + r * 80 + q * 16),        \
                 W + (size_t)(col0 + r) * 256 + k0 + q * 8);                     \
        }                                                                        \
        CP_COMMIT();                                                             \
    } while (0)

    LOADG(0, 0);

    const int arow = (lane & 7) + ((lane >> 3) & 1) * 8;
    const int aksh = ((lane >> 4) & 1) * 8;
    const int brow = (lane & 7) + ((lane >> 4) & 1) * 8;
    const int bksh = ((lane >> 3) & 1) * 8;

    for (int s = 0; s < 8; s++) {
        const int cur = s & 1;
        CP_WAIT0();
        __syncthreads();
        if (s < 7) LOADG(s + 1, cur ^ 1);
#pragma unroll
        for (int kk = 0; kk < 2; kk++) {
            const int kb = kk * 16;
            uint32_t a[4][4];
#pragma unroll
            for (int mt = 0; mt < 4; mt++) {
                const int r = wm * 64 + mt * 16 + arow;
                const uint32_t aoff = (uint32_t)(cur * 10240 + r * 80 + (kb + aksh) * 2);
                LDM4(a[mt][0], a[mt][1], a[mt][2], a[mt][3], sb + aoff);
            }
#pragma unroll
            for (int ntp = 0; ntp < 2; ntp++) {
                const int nr = wn * 32 + ntp * 16 + brow;
                const uint32_t boff =
                    (uint32_t)(20480 + cur * 5120 + nr * 80 + (kb + bksh) * 2);
                uint32_t b[4];
                LDM4(b[0], b[1], b[2], b[3], sb + boff);
#pragma unroll
                for (int mt = 0; mt < 4; mt++) {
                    mma16h(c[mt][2 * ntp],     a[mt], b);
                    mma16h(c[mt][2 * ntp + 1], a[mt], b + 2);
                }
            }
        }
    }

    // ---- epilogue ----
#pragma unroll
    for (int mt = 0; mt < 4; mt++) {
        const int rbase = wm * 64 + mt * 16 + gid;
#pragma unroll
        for (int h8 = 0; h8 < 2; h8++) {
            const size_t grow = row0 + rbase + h8 * 8;
#pragma unroll
            for (int nt = 0; nt < 4; nt++) {
                const int cib = wn * 32 + nt * 8 + t4 * 2;
                const float v0 = c[mt][nt][h8 * 2 + 0];
                const float v1 = c[mt][nt][h8 * 2 + 1];
                if (mode) {
                    const float2 pbv = *(const float2*)(pb + col0 + cib);
                    float2 o2; o2.x = v0 + pbv.x; o2.y = v1 + pbv.y;
                    *(float2*)(outp + grow * 256 + col0 + cib) = o2;
                } else {
                    const int gc = col0 + cib;
                    const int region = gc >> 8;            // 0=q 1=k 2=v
                    const int c2 = gc & 255;
                    const float* bias = (region == 0) ? bq
                                       : (region == 1) ? bkv : (bkv + 256);
                    const float2 bv = *(const float2*)(bias + c2);
                    const float scl = (region == 0) ? 0.17677669529663687f : 1.0f;
                    __half* dst = (region == 0) ? g_qf : (region == 1) ? g_kf : g_vf;
                    const int win = (int)(grow >> 6), nn = (int)(grow & 63);
                    const int hh = c2 >> 5, d = c2 & 31;
                    const size_t di = (((size_t)win * NHEADS + hh) * NTOK + nn) * HD + d;
                    __half2 p = __floats2half2_rn((v0 + bv.x) * scl,
                                                  (v1 + bv.y) * scl);
                    *(uint32_t*)(dst + di) = *(uint32_t*)&p;
                }
            }
        }
    }
#undef LOADG
}

// ---------------------------------------------------------------------------
// Attention, all-single fp16 (R14 version). Block = one (b,h), 128 thr.
// smem bytes: Q 0, K 5120, V 10240; S 15360 + wid*2304. total 24576
// ---------------------------------------------------------------------------
__global__ __launch_bounds__(128) void attn_f16(const float* __restrict__ w)
{
    extern __shared__ __align__(16) char sm[];
    const uint32_t sb = s2u(sm);
    const int bh = blockIdx.x, h = bh & 7;
    const int t = threadIdx.x, lane = t & 31, wid = t >> 5;
    const int gid = lane >> 2, t4 = lane & 3;

    {
        const size_t gbase = (size_t)bh * 2048;
#pragma unroll
        for (int j = 0; j < 2; j++) {
            const int idx = j * 128 + t;
            const int r = idx >> 2, q = idx & 3;
            const uint32_t doff = (uint32_t)(r * 80 + q * 16);
            const size_t soff = gbase + r * 32 + q * 8;
            CP16(sb + doff,         g_qf + soff);
            CP16(sb + 5120 + doff,  g_kf + soff);
            CP16(sb + 10240 + doff, g_vf + soff);
        }
        CP_COMMIT();
    }
    CP_WAIT0();
    __syncthreads();

    const int arow = (lane & 7) + ((lane >> 3) & 1) * 8;
    const int aksh = ((lane >> 4) & 1) * 8;
    const int brow = (lane & 7) + ((lane >> 4) & 1) * 8;
    const int bksh = ((lane >> 3) & 1) * 8;
    const int vrow = (lane & 7) + ((lane >> 3) & 1) * 8;
    const int vcsh = ((lane >> 4) & 1) * 8;

    // ---- S = Q@K^T (single-term) ----
    float c[8][4];
#pragma unroll
    for (int nt = 0; nt < 8; nt++)
#pragma unroll
        for (int i = 0; i < 4; i++) c[nt][i] = 0.f;

#pragma unroll
    for (int kk = 0; kk < 2; kk++) {
        const int kb16 = kk * 16;
        uint32_t a[4];
        const uint32_t qoff = (uint32_t)((wid * 16 + arow) * 80 + (kb16 + aksh) * 2);
        LDM4(a[0], a[1], a[2], a[3], sb + qoff);
#pragma unroll
        for (int ntp = 0; ntp < 4; ntp++) {
            const uint32_t koff =
                (uint32_t)(5120 + (ntp * 16 + brow) * 80 + (kb16 + bksh) * 2);
            uint32_t bk[4];
            LDM4(bk[0], bk[1], bk[2], bk[3], sb + koff);
            mma16h(c[2 * ntp],     a, bk);
            mma16h(c[2 * ntp + 1], a, bk + 2);
        }
    }

    // ---- bias add ----
    const int r0 = wid * 16 + gid;
    const float* b0p = g_bias + ((size_t)h * 64 + r0) * 64;
    const float* b1p = b0p + 8 * 64;
#pragma unroll
    for (int nt = 0; nt < 8; nt++) {
        const int cc = nt * 8 + 2 * t4;
        const float2 x0 = *(const float2*)(b0p + cc);
        const float2 x1 = *(const float2*)(b1p + cc);
        c[nt][0] += x0.x; c[nt][1] += x0.y;
        c[nt][2] += x1.x; c[nt][3] += x1.y;
    }

    // ---- softmax sums ----
    float p0 = 0.f, p1 = 0.f;
#pragma unroll
    for (int nt = 0; nt < 8; nt++) {
        p0 += __expf(c[nt][0]) + __expf(c[nt][1]);
        p1 += __expf(c[nt][2]) + __expf(c[nt][3]);
    }
    p0 += __shfl_xor_sync(0xFFFFFFFF, p0, 1);
    p0 += __shfl_xor_sync(0xFFFFFFFF, p0, 2);
    p1 += __shfl_xor_sync(0xFFFFFFFF, p1, 1);
    p1 += __shfl_xor_sync(0xFFFFFFFF, p1, 2);

    const float w0 = w[0], w1 = w[1];
    const float wmx = fmaxf(w0, w1);
    const float e0 = __expf(w0 - wmx), e1 = __expf(w1 - wmx);
    const float winv = 1.f / (e0 + e1);
    const float ww0 = e0 * winv, ww1 = e1 * winv;
    const float k00 = ww0 / p0, k01 = ww0 / p1;

    // ---- combined weights -> S single fp16 smem ----
    const uint32_t sh0 = 15360 + wid * 2304;
#pragma unroll
    for (int nt = 0; nt < 8; nt++) {
        const int cc = nt * 8 + 2 * t4;
        const float q00 = fmaxf(c[nt][0], 0.f), q01 = fmaxf(c[nt][1], 0.f);
        const float q10 = fmaxf(c[nt][2], 0.f), q11 = fmaxf(c[nt][3], 0.f);
        const float a0 = __expf(c[nt][0]) * k00 + q00 * q00 * ww1;
        const float a1 = __expf(c[nt][1]) * k00 + q01 * q01 * ww1;
        const float a2 = __expf(c[nt][2]) * k01 + q10 * q10 * ww1;
        const float a3 = __expf(c[nt][3]) * k01 + q11 * q11 * ww1;
        __half2 h01 = __floats2half2_rn(a0, a1);
        __half2 h23 = __floats2half2_rn(a2, a3);
        *(uint32_t*)(sm + sh0 + gid * 144 + cc * 2) = *(uint32_t*)&h01;
        *(uint32_t*)(sm + sh0 + (gid + 8) * 144 + cc * 2) = *(uint32_t*)&h23;
    }
    __syncwarp();

    // ---- O = A @ V (single-term), V via ldmatrix.trans ----
    float o[4][4];
#pragma unroll
    for (int nt = 0; nt < 4; nt++)
#pragma unroll
        for (int i = 0; i < 4; i++) o[nt][i] = 0.f;

#pragma unroll
    for (int kc = 0; kc < 4; kc++) {
        const int kb16 = kc * 16;
        uint32_t a[4];
        const uint32_t soff = (uint32_t)(arow * 144 + (kb16 + aksh) * 2);
        LDM4(a[0], a[1], a[2], a[3], sb + sh0 + soff);
#pragma unroll
        for (int ntp = 0; ntp < 2; ntp++) {
            const uint32_t voff =
                (uint32_t)(10240 + (kb16 + vrow) * 80 + (ntp * 16 + vcsh) * 2);
            uint32_t bv[4];
            LDM4T(bv[0], bv[1], bv[2], bv[3], sb + voff);
            mma16h(o[2 * ntp],     a, bv);
            mma16h(o[2 * ntp + 1], a, bv + 2);
        }
    }

    // ---- write O fp16 ----
    const size_t obase = ((size_t)(bh >> 3) * 64) * 256 + h * 32;
#pragma unroll
    for (int nt = 0; nt < 4; nt++) {
        const int d = nt * 8 + 2 * t4;
        __half2 v0 = __floats2half2_rn(o[nt][0], o[nt][1]);
        __half2 v1 = __floats2half2_rn(o[nt][2], o[nt][3]);
        *(uint32_t*)(g_of + obase + (size_t)r0 * 256 + d) = *(uint32_t*)&v0;
        *(uint32_t*)(g_of + obase + (size_t)(r0 + 8) * 256 + d) = *(uint32_t*)&v1;
    }
}

// ---------------------------------------------------------------------------
extern "C" void kernel_launch(void* const* d_in, const int* in_sizes, int n_in,
                              void* d_out, int out_size)
{
    const float* x   = (const float*)d_in[0];
    const float* wq  = (const float*)d_in[1];
    const float* bq  = (const float*)d_in[2];
    const float* wkv = (const float*)d_in[3];
    const float* bkv = (const float*)d_in[4];
    const float* bt  = (const float*)d_in[5];
    const float* w   = (const float*)d_in[6];
    const float* pw  = (const float*)d_in[7];
    const float* pb  = (const float*)d_in[8];
    const int*   ri  = (const int*)d_in[9];
    float* out = (float*)d_out;

    __half *xf, *of, *wqf, *wpf;
    cudaGetSymbolAddress((void**)&xf,  g_xf);
    cudaGetSymbolAddress((void**)&of,  g_of);
    cudaGetSymbolAddress((void**)&wqf, g_wqf);
    cudaGetSymbolAddress((void**)&wpf, g_wpf);

    prep_all<<<66688, 256>>>(x, wq, wkv, pw, bt, ri);
    mm_fp16<<<dim3(12, NROWS / 128), 128, 30720>>>(xf, wqf, bq, bkv,
                                                   nullptr, nullptr, 0);
    attn_f16<<<NBATCH * NHEADS, 128, 24576>>>(w);
    mm_fp16<<<dim3(4, NROWS / 128), 128, 30720>>>(of, wpf, nullptr, nullptr,
                                                  pb, out, 1);
}